// round 16
// baseline (speedup 1.0000x reference)
#include <cuda_runtime.h>

#define SEQ   512
#define DIM   512
#define HEADS 8
#define DH    64
#define DR    16
#define HD    128

// ---------------- device scratch ----------------
__device__ float g_xn  [SEQ*DIM];
__device__ float g_qkv [SEQ*3*DIM];        // q1|k1|v1
__device__ float g_aq  [SEQ*HD];
__device__ float g_ak  [SEQ*HD];
__device__ float g_av  [SEQ*HD];
__device__ float g_dots[HEADS*SEQ*SEQ];    // dots2 lower-tri, then attn in place
__device__ float g_uv  [(size_t)SEQ*SEQ*HD];
__device__ float g_cat [SEQ*640];          // [out1 | out2] concatenated, stride 640
__device__ float g_wcat[640*512];          // [0.5*w_out ; 0.5*(w_v3@w_out)]

// ---------------- helpers ----------------
__device__ __forceinline__ float to_tf32(float x) {
    unsigned u;
    asm("cvt.rna.tf32.f32 %0, %1;" : "=r"(u) : "f"(x));
    return __uint_as_float(u);
}
__device__ __forceinline__ void mma_tf32(float c[4], unsigned a0, unsigned a1, unsigned a2, unsigned a3,
                                         unsigned b0, unsigned b1) {
    asm volatile("mma.sync.aligned.m16n8k8.row.col.f32.tf32.tf32.f32 "
                 "{%0,%1,%2,%3}, {%4,%5,%6,%7}, {%8,%9}, {%0,%1,%2,%3};"
                 : "+f"(c[0]), "+f"(c[1]), "+f"(c[2]), "+f"(c[3])
                 : "r"(a0), "r"(a1), "r"(a2), "r"(a3), "r"(b0), "r"(b1));
}

// ---------------- layernorm ----------------
__global__ void __launch_bounds__(256) ln_kernel(const float* __restrict__ x,
                                                 const float* __restrict__ w,
                                                 const float* __restrict__ b) {
    int row = blockIdx.x;
    int tid = threadIdx.x;
    const float* xr = x + row*DIM;
    __shared__ float red[20];
    float v0 = xr[tid], v1 = xr[tid+256];
    float s = v0 + v1;
    #pragma unroll
    for (int o=16;o;o>>=1) s += __shfl_xor_sync(0xffffffffu, s, o);
    if ((tid&31)==0) red[tid>>5] = s;
    __syncthreads();
    if (tid < 8) {
        s = red[tid];
        #pragma unroll
        for (int o=4;o;o>>=1) s += __shfl_xor_sync(0xffu, s, o);
        if (tid==0) red[16] = s;
    }
    __syncthreads();
    float mu = red[16] * (1.0f/DIM);
    float d0 = v0-mu, d1 = v1-mu;
    float q = d0*d0 + d1*d1;
    #pragma unroll
    for (int o=16;o;o>>=1) q += __shfl_xor_sync(0xffffffffu, q, o);
    if ((tid&31)==0) red[8 + (tid>>5)] = q;
    __syncthreads();
    if (tid < 8) {
        q = red[8+tid];
        #pragma unroll
        for (int o=4;o;o>>=1) q += __shfl_xor_sync(0xffu, q, o);
        if (tid==0) red[17] = q;
    }
    __syncthreads();
    float inv = rsqrtf(red[17]*(1.0f/DIM) + 1e-5f);
    g_xn[row*DIM + tid]     = d0*inv*w[tid]     + b[tid];
    g_xn[row*DIM + tid+256] = d1*inv*w[tid+256] + b[tid+256];
}

// ---------------- generic tf32 MMA GEMM: C[M,N] = A[M,K] @ B[K,N] ----------------
// 128 threads = 4 warps (2m x 2n), warp tile m32 x n32, block tile 64x64, BK=32.
// EPI: 0 none, 2 C=AB+bias[col], 3 C=to_tf32(AB), 4 C=0.5*AB
struct SmemGemm { float sA[64][36]; float sB[32][72]; };

template<int EPI>
__device__ __forceinline__ void gemm_body(const float* __restrict__ A, const float* __restrict__ B,
                                          float* __restrict__ C, int N, int K,
                                          const float* __restrict__ add,
                                          SmemGemm& sm, int m0, int n0) {
    int tid = threadIdx.x;
    int warp = tid>>5, lane = tid&31;
    int qrow = lane>>2, qcol = lane&3;
    int m_base = (warp&1)*32, n_base = (warp>>1)*32;
    float acc[8][4] = {};
    for (int kc = 0; kc < K; kc += 32) {
        __syncthreads();
        #pragma unroll
        for (int q=0;q<4;q++) {
            int idx = q*128+tid; int r = idx>>3, c4 = idx&7;
            float4 v = *(const float4*)(A + (size_t)(m0+r)*K + kc + c4*4);
            sm.sA[r][c4*4+0]=to_tf32(v.x); sm.sA[r][c4*4+1]=to_tf32(v.y);
            sm.sA[r][c4*4+2]=to_tf32(v.z); sm.sA[r][c4*4+3]=to_tf32(v.w);
        }
        #pragma unroll
        for (int q=0;q<4;q++) {
            int idx = q*128+tid; int r = idx>>4, c4 = idx&15;
            float4 v = *(const float4*)(B + (size_t)(kc+r)*N + n0 + c4*4);
            sm.sB[r][c4*4+0]=to_tf32(v.x); sm.sB[r][c4*4+1]=to_tf32(v.y);
            sm.sB[r][c4*4+2]=to_tf32(v.z); sm.sB[r][c4*4+3]=to_tf32(v.w);
        }
        __syncthreads();
        #pragma unroll
        for (int ks=0; ks<4; ks++) {
            int k0 = ks*8;
            unsigned a[2][4];
            #pragma unroll
            for (int mf=0; mf<2; mf++) {
                int mr = m_base + mf*16 + qrow;
                a[mf][0] = __float_as_uint(sm.sA[mr  ][k0+qcol  ]);
                a[mf][1] = __float_as_uint(sm.sA[mr+8][k0+qcol  ]);
                a[mf][2] = __float_as_uint(sm.sA[mr  ][k0+qcol+4]);
                a[mf][3] = __float_as_uint(sm.sA[mr+8][k0+qcol+4]);
            }
            #pragma unroll
            for (int nf=0; nf<4; nf++) {
                unsigned b0 = __float_as_uint(sm.sB[k0+qcol  ][n_base+nf*8+qrow]);
                unsigned b1 = __float_as_uint(sm.sB[k0+qcol+4][n_base+nf*8+qrow]);
                mma_tf32(acc[nf],   a[0][0],a[0][1],a[0][2],a[0][3], b0,b1);
                mma_tf32(acc[4+nf], a[1][0],a[1][1],a[1][2],a[1][3], b0,b1);
            }
        }
    }
    #pragma unroll
    for (int mf=0; mf<2; mf++) {
        #pragma unroll
        for (int nf=0; nf<4; nf++) {
            int col = n0 + n_base + nf*8 + 2*qcol;
            int r0 = m0 + m_base + mf*16 + qrow, r1 = r0 + 8;
            float2 v0 = make_float2(acc[mf*4+nf][0], acc[mf*4+nf][1]);
            float2 v1 = make_float2(acc[mf*4+nf][2], acc[mf*4+nf][3]);
            if (EPI==2) {
                v0.x += add[col]; v0.y += add[col+1];
                v1.x += add[col]; v1.y += add[col+1];
            } else if (EPI==3) {
                v0.x = to_tf32(v0.x); v0.y = to_tf32(v0.y);
                v1.x = to_tf32(v1.x); v1.y = to_tf32(v1.y);
            } else if (EPI==4) {
                v0.x *= 0.5f; v0.y *= 0.5f;
                v1.x *= 0.5f; v1.y *= 0.5f;
            }
            *(float2*)(C + (size_t)r0*N + col) = v0;
            *(float2*)(C + (size_t)r1*N + col) = v1;
        }
    }
}

template<int EPI>
__global__ void __launch_bounds__(128) mma_gemm(const float* __restrict__ A, const float* __restrict__ B,
                                                float* __restrict__ C, int N, int K,
                                                const float* __restrict__ add) {
    __shared__ SmemGemm sm;
    gemm_body<EPI>(A, B, C, N, K, add, sm, blockIdx.y*64, blockIdx.x*64);
}

// fused qkv + q1/k1/v1 projections: 240 blocks, 1D grid.
// id<192: qkv tile; else projection tile (z selects weight/output, EPI=3 pre-round)
__global__ void __launch_bounds__(128) fused_proj(const float* __restrict__ A,
                                                  const float* __restrict__ Wq,
                                                  const float* __restrict__ B0, const float* __restrict__ B1,
                                                  const float* __restrict__ B2,
                                                  float* Cq, float* C0, float* C1, float* C2) {
    __shared__ SmemGemm sm;
    int id = blockIdx.x;
    if (id < 192) {
        int x = id % 24, y = id / 24;
        gemm_body<0>(A, Wq, Cq, 1536, 512, nullptr, sm, y*64, x*64);
    } else {
        int t = id - 192;
        int z = t >> 4, r = t & 15;
        int x = r & 1, y = r >> 1;
        const float* B = z==0 ? B0 : (z==1 ? B1 : B2);
        float* C       = z==0 ? C0 : (z==1 ? C1 : C2);
        gemm_body<3>(A, B, C, 128, 512, nullptr, sm, y*64, x*64);
    }
}

// g_wcat rows 0..511 = 0.5*w_out
__global__ void __launch_bounds__(256) wcopy_kernel(const float* __restrict__ w) {
    int i = blockIdx.x*256 + threadIdx.x;
    float4 v = ((const float4*)w)[i];
    v.x *= 0.5f; v.y *= 0.5f; v.z *= 0.5f; v.w *= 0.5f;
    ((float4*)g_wcat)[i] = v;
}

// ---------------- per-diagonal rel-projection via tf32 MMA (frozen) ----------------
#define PBUF_FLOATS 2560
#define DIAG_SMEM (128*132*4 + 2*PBUF_FLOATS*4)

__global__ void __launch_bounds__(256,2) diag_mma(const float* __restrict__ Pq,
                                                  const float* __restrict__ Pk,
                                                  const float* __restrict__ Pv) {
    int d  = blockIdx.y;
    int nj = SEQ - d;
    int j0 = blockIdx.x * 128;
    if (j0 >= nj) return;
    int nvalid = min(128, nj - j0);

    extern __shared__ float dsm[];
    float (*sA)[132] = (float(*)[132])dsm;
    float* sB = dsm + 128*132;

    int tid = threadIdx.x, warp = tid>>5, lane = tid&31;
    int qrow = lane>>2, qcol = lane&3;
    int m_base = (warp&3)*32;
    bool act = m_base < nvalid;

    auto loadA = [&](const float* __restrict__ Ab, int rowbase) {
        __syncthreads();
        #pragma unroll
        for (int q=0;q<16;q++) {
            int idx = q*256+tid; int r = idx>>5, c4 = idx&31;
            float4 v = make_float4(0.f,0.f,0.f,0.f);
            if (r < nvalid) v = *(const float4*)(Ab + (rowbase+r)*HD + c4*4);
            *(float4*)&sA[r][c4*4] = v;
        }
    };

    auto gemm_h = [&](const float* __restrict__ P, int c0, float acc[8][4]) {
        int nf0 = (warp>>2)*4;
        int pr = tid>>4, L = tid&15;
        const float* Pt = P + pr*HD + c0 + L*4;
        int rowbase_f = ((pr>>3)*2 + ((pr>>2)&1))*32 + (pr&3);
        int nf_f = L>>1;
        int qoff = (L&1)*4;
        auto stchunk = [&](float* buf, float4 v) {
            buf[(rowbase_f + (qoff+0)*4)*12 + nf_f] = to_tf32(v.x);
            buf[(rowbase_f + (qoff+1)*4)*12 + nf_f] = to_tf32(v.y);
            buf[(rowbase_f + (qoff+2)*4)*12 + nf_f] = to_tf32(v.z);
            buf[(rowbase_f + (qoff+3)*4)*12 + nf_f] = to_tf32(v.w);
        };
        float4 pre = *(const float4*)Pt;
        stchunk(sB, pre);
        pre = *(const float4*)(Pt + 16*HD);
        __syncthreads();
        int cur = 0;
        for (int kc=0; kc<128; kc+=16) {
            int nxt = cur^1;
            if (kc + 16 < 128) {
                stchunk(sB + nxt*PBUF_FLOATS, pre);
                if (kc + 32 < 128) pre = *(const float4*)(Pt + (kc+32)*HD);
            }
            if (act) {
                const float* buf = sB + cur*PBUF_FLOATS;
                #pragma unroll
                for (int ks=0; ks<2; ks++) {
                    int k0 = kc + ks*8;
                    unsigned a[2][4];
                    #pragma unroll
                    for (int mf=0; mf<2; mf++) {
                        int mr = m_base + mf*16 + qrow;
                        a[mf][0] = __float_as_uint(sA[mr  ][k0+qcol  ]);
                        a[mf][1] = __float_as_uint(sA[mr+8][k0+qcol  ]);
                        a[mf][2] = __float_as_uint(sA[mr  ][k0+qcol+4]);
                        a[mf][3] = __float_as_uint(sA[mr+8][k0+qcol+4]);
                    }
                    float4 b0p = *(const float4*)(buf + ((ks*2+0)*32 + lane)*12 + nf0);
                    float4 b1p = *(const float4*)(buf + ((ks*2+1)*32 + lane)*12 + nf0);
                    const float* b0a = (const float*)&b0p;
                    const float* b1a = (const float*)&b1p;
                    #pragma unroll
                    for (int nf=0; nf<4; nf++) {
                        unsigned b0 = __float_as_uint(b0a[nf]);
                        unsigned b1 = __float_as_uint(b1a[nf]);
                        mma_tf32(acc[nf],   a[0][0],a[0][1],a[0][2],a[0][3], b0,b1);
                        mma_tf32(acc[4+nf], a[1][0],a[1][1],a[1][2],a[1][3], b0,b1);
                    }
                }
            }
            __syncthreads();
            cur = nxt;
        }
    };

    auto dots2_h = [&](float accQ[8][4], float accK[8][4], int half) {
        if (!act) return;
        #pragma unroll
        for (int mf=0; mf<2; mf++) {
            #pragma unroll
            for (int hh=0; hh<2; hh++) {
                int f0 = mf*4 + 2*hh, f1 = f0 + 1;
                float p0 = accQ[f0][0]*accK[f0][0] + accQ[f0][1]*accK[f0][1]
                         + accQ[f1][0]*accK[f1][0] + accQ[f1][1]*accK[f1][1];
                float p1 = accQ[f0][2]*accK[f0][2] + accQ[f0][3]*accK[f0][3]
                         + accQ[f1][2]*accK[f1][2] + accQ[f1][3]*accK[f1][3];
                p0 += __shfl_xor_sync(0xffffffffu, p0, 1);
                p0 += __shfl_xor_sync(0xffffffffu, p0, 2);
                p1 += __shfl_xor_sync(0xffffffffu, p1, 1);
                p1 += __shfl_xor_sync(0xffffffffu, p1, 2);
                if (qcol == 0) {
                    int h = half*4 + ((warp>>2)<<1) + hh;
                    int r0 = m_base + mf*16 + qrow;
                    if (r0 < nvalid) { int j = j0 + r0; g_dots[(size_t)h*SEQ*SEQ + (size_t)(j+d)*SEQ + j] = p0; }
                    int r1 = r0 + 8;
                    if (r1 < nvalid) { int j = j0 + r1; g_dots[(size_t)h*SEQ*SEQ + (size_t)(j+d)*SEQ + j] = p1; }
                }
            }
        }
    };

    const float* Pk_d = Pk + (size_t)d*HD*HD;
    const float* Pq_d = Pq + (size_t)(SEQ-1-d)*HD*HD;

    float accK[8][4], accQ[8][4];

    #pragma unroll
    for (int f=0;f<8;f++){accK[f][0]=0;accK[f][1]=0;accK[f][2]=0;accK[f][3]=0;}
    loadA(g_ak, j0);
    gemm_h(Pk_d, 0, accK);
    #pragma unroll
    for (int f=0;f<8;f++){accQ[f][0]=0;accQ[f][1]=0;accQ[f][2]=0;accQ[f][3]=0;}
    loadA(g_aq, j0 + d);
    gemm_h(Pq_d, 0, accQ);
    dots2_h(accQ, accK, 0);

    #pragma unroll
    for (int f=0;f<8;f++){accQ[f][0]=0;accQ[f][1]=0;accQ[f][2]=0;accQ[f][3]=0;}
    gemm_h(Pq_d, 64, accQ);
    #pragma unroll
    for (int f=0;f<8;f++){accK[f][0]=0;accK[f][1]=0;accK[f][2]=0;accK[f][3]=0;}
    loadA(g_ak, j0);
    gemm_h(Pk_d, 64, accK);
    dots2_h(accQ, accK, 1);

    {
        int nf0 = (warp>>2)*8;
        float acc[16][4];
        #pragma unroll
        for (int f=0;f<16;f++){acc[f][0]=0;acc[f][1]=0;acc[f][2]=0;acc[f][3]=0;}
        loadA(g_av, j0);
        const float* P = Pv + (size_t)d*HD*HD;
        int pr = tid>>5, pc4 = tid&31;
        const float* Pt = P + pr*HD + pc4*4;
        int khalf_f = (pr>>2)&1, kq_f = pr&3;
        int nf_f = pc4>>1;
        int qoff = (pc4&1)*4;
        auto stchunkV = [&](float* buf, float4 v, int q) {
            int rowbase_f = (q*2 + khalf_f)*32 + kq_f;
            buf[(rowbase_f + (qoff+0)*4)*20 + nf_f] = to_tf32(v.x);
            buf[(rowbase_f + (qoff+1)*4)*20 + nf_f] = to_tf32(v.y);
            buf[(rowbase_f + (qoff+2)*4)*20 + nf_f] = to_tf32(v.z);
            buf[(rowbase_f + (qoff+3)*4)*20 + nf_f] = to_tf32(v.w);
        };
        float4 pre[2];
        #pragma unroll
        for (int q=0;q<2;q++) pre[q] = *(const float4*)(Pt + q*8*HD);
        #pragma unroll
        for (int q=0;q<2;q++) stchunkV(sB, pre[q], q);
        #pragma unroll
        for (int q=0;q<2;q++) pre[q] = *(const float4*)(Pt + (16 + q*8)*HD);
        __syncthreads();
        int cur = 0;
        for (int kc=0; kc<128; kc+=16) {
            int nxt = cur^1;
            if (kc + 16 < 128) {
                #pragma unroll
                for (int q=0;q<2;q++) stchunkV(sB + nxt*PBUF_FLOATS, pre[q], q);
                if (kc + 32 < 128) {
                    #pragma unroll
                    for (int q=0;q<2;q++) pre[q] = *(const float4*)(Pt + (kc+32+q*8)*HD);
                }
            }
            if (act) {
                const float* buf = sB + cur*PBUF_FLOATS;
                #pragma unroll
                for (int ks=0; ks<2; ks++) {
                    int k0 = kc + ks*8;
                    unsigned a[2][4];
                    #pragma unroll
                    for (int mf=0; mf<2; mf++) {
                        int mr = m_base + mf*16 + qrow;
                        a[mf][0] = __float_as_uint(sA[mr  ][k0+qcol  ]);
                        a[mf][1] = __float_as_uint(sA[mr+8][k0+qcol  ]);
                        a[mf][2] = __float_as_uint(sA[mr  ][k0+qcol+4]);
                        a[mf][3] = __float_as_uint(sA[mr+8][k0+qcol+4]);
                    }
                    float4 b0p0 = *(const float4*)(buf + ((ks*2+0)*32 + lane)*20 + nf0);
                    float4 b0p1 = *(const float4*)(buf + ((ks*2+0)*32 + lane)*20 + nf0 + 4);
                    float4 b1p0 = *(const float4*)(buf + ((ks*2+1)*32 + lane)*20 + nf0);
                    float4 b1p1 = *(const float4*)(buf + ((ks*2+1)*32 + lane)*20 + nf0 + 4);
                    const float* b0a = (const float*)&b0p0;
                    const float* b0b = (const float*)&b0p1;
                    const float* b1a = (const float*)&b1p0;
                    const float* b1b = (const float*)&b1p1;
                    #pragma unroll
                    for (int nf=0; nf<8; nf++) {
                        unsigned b0 = __float_as_uint(nf < 4 ? b0a[nf] : b0b[nf-4]);
                        unsigned b1 = __float_as_uint(nf < 4 ? b1a[nf] : b1b[nf-4]);
                        mma_tf32(acc[nf],   a[0][0],a[0][1],a[0][2],a[0][3], b0,b1);
                        mma_tf32(acc[8+nf], a[1][0],a[1][1],a[1][2],a[1][3], b0,b1);
                    }
                }
            }
            __syncthreads();
            cur = nxt;
        }
        if (act) {
            int n_base = (warp>>2)*64;
            #pragma unroll
            for (int mf=0; mf<2; mf++) {
                #pragma unroll
                for (int nf=0; nf<8; nf++) {
                    int col = n_base + nf*8 + 2*qcol;
                    int r0 = m_base + mf*16 + qrow;
                    if (r0 < nvalid)
                        *(float2*)(g_uv + ((size_t)d*SEQ + j0 + r0)*HD + col) = make_float2(acc[mf*8+nf][0], acc[mf*8+nf][1]);
                    int r1 = r0 + 8;
                    if (r1 < nvalid)
                        *(float2*)(g_uv + ((size_t)d*SEQ + j0 + r1)*HD + col) = make_float2(acc[mf*8+nf][2], acc[mf*8+nf][3]);
                }
            }
        }
    }
}

// ---------------- dots1 + combine + causal softmax + fused out1 -> g_cat ----------------
__global__ void __launch_bounds__(256) attn_kernel() {
    int h  = blockIdx.y;
    int i0 = blockIdx.x * 16;
    __shared__ float sQ[16][68];
    __shared__ float sK[32][68];
    __shared__ float sD[16][512];
    int tid = threadIdx.x;
    {   int r = tid>>4, c4 = tid&15;
        *(float4*)&sQ[r][c4*4] = *(const float4*)(g_qkv + (i0+r)*1536 + h*64 + c4*4); }
    int r2 = tid>>4, jj = tid&15;
    for (int jc = 0; jc < 512; jc += 32) {
        __syncthreads();
        #pragma unroll
        for (int q=0; q<2; q++) {
            int idx = q*256 + tid; int r = idx>>4, c4 = idx&15;
            *(float4*)&sK[r][c4*4] = *(const float4*)(g_qkv + (jc+r)*1536 + 512 + h*64 + c4*4);
        }
        __syncthreads();
        float a0 = 0.f, a1 = 0.f;
        #pragma unroll
        for (int c4 = 0; c4 < 16; c4++) {
            float4 qv = *(const float4*)&sQ[r2][c4*4];
            float4 k0 = *(const float4*)&sK[jj][c4*4];
            float4 k1 = *(const float4*)&sK[jj+16][c4*4];
            a0 += qv.x*k0.x + qv.y*k0.y + qv.z*k0.z + qv.w*k0.w;
            a1 += qv.x*k1.x + qv.y*k1.y + qv.z*k1.z + qv.w*k1.w;
        }
        sD[r2][jc+jj]    = a0;
        sD[r2][jc+jj+16] = a1;
    }
    __syncthreads();
    int w = tid>>5, lane = tid&31;
    for (int rr = 2*w; rr < 2*w+2; rr++) {
        int i = i0 + rr;
        float vals[16];
        float m = -1e30f;
        #pragma unroll
        for (int t=0; t<16; t++) {
            int j = lane + t*32;
            float dv = -1e30f;
            if (j <= i)
                dv = 0.0625f * (sD[rr][j] + g_dots[(size_t)h*SEQ*SEQ + (size_t)i*SEQ + j]);
            vals[t] = dv;
            m = fmaxf(m, dv);
        }
        #pragma unroll
        for (int o=16;o;o>>=1) m = fmaxf(m, __shfl_xor_sync(0xffffffffu, m, o));
        float s = 0.f;
        #pragma unroll
        for (int t=0; t<16; t++) {
            float e = (vals[t] > -1e29f) ? __expf(vals[t]-m) : 0.f;
            vals[t] = e; s += e;
        }
        #pragma unroll
        for (int o=16;o;o>>=1) s += __shfl_xor_sync(0xffffffffu, s, o);
        float inv = 1.f / s;
        #pragma unroll
        for (int t=0; t<16; t++) {
            int j = lane + t*32;
            float av = vals[t]*inv;
            g_dots[(size_t)h*SEQ*SEQ + (size_t)i*SEQ + j] = av;
            sD[rr][j] = av;
        }
    }
    __syncthreads();
    // fused out1 -> g_cat cols [h*64, h*64+64), row stride 640
    {
        int tx = tid & 15;
        float acc0=0.f, acc1=0.f, acc2=0.f, acc3=0.f;
        for (int jc = 0; jc < 512; jc += 32) {
            __syncthreads();
            #pragma unroll
            for (int q=0; q<2; q++) {
                int idx = q*256 + tid; int r = idx>>4, c4 = idx&15;
                *(float4*)&sK[r][c4*4] = *(const float4*)(g_qkv + (jc+r)*1536 + 1024 + h*64 + c4*4);
            }
            __syncthreads();
            #pragma unroll
            for (int k=0; k<32; k++) {
                float a = sD[r2][jc+k];
                float4 v4 = *(float4*)&sK[k][tx*4];
                acc0 += a*v4.x; acc1 += a*v4.y; acc2 += a*v4.z; acc3 += a*v4.w;
            }
        }
        *(float4*)(g_cat + (size_t)(i0+r2)*640 + h*64 + tx*4) = make_float4(acc0,acc1,acc2,acc3);
    }
}

// ---------------- out2 -> g_cat cols [512, 640) ----------------
__global__ void __launch_bounds__(1024) out2_kernel() {
    int i = blockIdx.x;
    int tid = threadIdx.x;
    int c = tid & 127;
    int part = tid >> 7;
    int h = c >> 4;
    const float* arow = g_dots + (size_t)h*SEQ*SEQ + (size_t)i*SEQ;
    int len = i + 1;
    int chunk = (len + 7) >> 3;
    int jb = part*chunk, je = min(len, jb + chunk);
    float a0=0.f, a1=0.f, a2=0.f, a3=0.f;
    int j = jb;
    for (; j+4 <= je; j += 4) {
        a0 += arow[j]   * g_uv[((size_t)(i-j  )*SEQ + j  )*HD + c];
        a1 += arow[j+1] * g_uv[((size_t)(i-j-1)*SEQ + j+1)*HD + c];
        a2 += arow[j+2] * g_uv[((size_t)(i-j-2)*SEQ + j+2)*HD + c];
        a3 += arow[j+3] * g_uv[((size_t)(i-j-3)*SEQ + j+3)*HD + c];
    }
    for (; j < je; j++)
        a0 += arow[j] * g_uv[((size_t)(i-j)*SEQ + j)*HD + c];
    __shared__ float red[1024];
    red[tid] = (a0+a1) + (a2+a3);
    __syncthreads();
    if (part < 4) red[tid] += red[tid + 512];
    __syncthreads();
    if (part < 2) red[tid] += red[tid + 256];
    __syncthreads();
    if (part == 0)
        g_cat[(size_t)i*640 + 512 + c] = red[c] + red[c + 128];
}

// ---------------- launch ----------------
extern "C" void kernel_launch(void* const* d_in, const int* in_sizes, int n_in,
                              void* d_out, int out_size) {
    const float* x     = (const float*)d_in[0];
    const float* ln_w  = (const float*)d_in[1];
    const float* ln_b  = (const float*)d_in[2];
    const float* w_qkv = (const float*)d_in[3];
    const float* w_q1  = (const float*)d_in[4];
    const float* p_q2  = (const float*)d_in[5];
    const float* w_k1  = (const float*)d_in[6];
    const float* p_k2  = (const float*)d_in[7];
    const float* w_v1  = (const float*)d_in[8];
    const float* p_v2  = (const float*)d_in[9];
    const float* w_v3  = (const float*)d_in[10];
    const float* w_out = (const float*)d_in[11];
    const float* b_out = (const float*)d_in[12];
    float* out = (float*)d_out;

    float *p_xn, *p_qkvb, *p_aq, *p_ak, *p_av, *p_cat, *p_wcat;
    cudaGetSymbolAddress((void**)&p_xn,   g_xn);
    cudaGetSymbolAddress((void**)&p_qkvb, g_qkv);
    cudaGetSymbolAddress((void**)&p_aq,   g_aq);
    cudaGetSymbolAddress((void**)&p_ak,   g_ak);
    cudaGetSymbolAddress((void**)&p_av,   g_av);
    cudaGetSymbolAddress((void**)&p_cat,  g_cat);
    cudaGetSymbolAddress((void**)&p_wcat, g_wcat);

    cudaFuncSetAttribute(diag_mma, cudaFuncAttributeMaxDynamicSharedMemorySize, DIAG_SMEM);

    // weight prep (inputs only; runs off the critical path first)
    wcopy_kernel<<<256, 256>>>(w_out);                                   // rows 0..511 = 0.5*w_out
    mma_gemm<4><<<dim3(8,2), 128>>>(w_v3, w_out, p_wcat + 512*512, 512, 512, nullptr); // rows 512..639 = 0.5*(w_v3@w_out)

    ln_kernel<<<512, 256>>>(x, ln_w, ln_b);

    // qkv + projections in one launch
    fused_proj<<<240, 128>>>(p_xn, w_qkv, w_q1, w_k1, w_v1,
                             p_qkvb, p_aq, p_ak, p_av);

    diag_mma<<<dim3(4,512), 256, DIAG_SMEM>>>(p_q2, p_k2, p_v2);

    attn_kernel<<<dim3(32,8), 256>>>();   // includes fused out1 -> g_cat
    out2_kernel<<<512, 1024>>>();         // -> g_cat cols 512..639

    // out = g_cat @ g_wcat + b_out   (512 x 512 x 640)
    mma_gemm<2><<<dim3(8,8), 128>>>(p_cat, p_wcat, out, 512, 640, b_out);
}

// round 17
// speedup vs baseline: 1.0887x; 1.0887x over previous
#include <cuda_runtime.h>

#define SEQ   512
#define DIM   512
#define HEADS 8
#define DH    64
#define DR    16
#define HD    128

// ---------------- device scratch ----------------
__device__ float g_xn  [SEQ*DIM];
__device__ float g_qkv [SEQ*3*DIM];        // q1|k1|v1
__device__ float g_aq  [SEQ*HD];
__device__ float g_ak  [SEQ*HD];
__device__ float g_av  [SEQ*HD];
__device__ float g_dots[HEADS*SEQ*SEQ];    // dots2 lower-tri, then attn in place
__device__ float g_uv  [(size_t)SEQ*SEQ*HD];
__device__ float g_cat [SEQ*640];          // [out1 | out2] concatenated, stride 640
__device__ float g_wcat[640*512];          // [0.5*w_out ; 0.5*(w_v3@w_out)]

// ---------------- helpers ----------------
__device__ __forceinline__ float to_tf32(float x) {
    unsigned u;
    asm("cvt.rna.tf32.f32 %0, %1;" : "=r"(u) : "f"(x));
    return __uint_as_float(u);
}
__device__ __forceinline__ void mma_tf32(float c[4], unsigned a0, unsigned a1, unsigned a2, unsigned a3,
                                         unsigned b0, unsigned b1) {
    asm volatile("mma.sync.aligned.m16n8k8.row.col.f32.tf32.tf32.f32 "
                 "{%0,%1,%2,%3}, {%4,%5,%6,%7}, {%8,%9}, {%0,%1,%2,%3};"
                 : "+f"(c[0]), "+f"(c[1]), "+f"(c[2]), "+f"(c[3])
                 : "r"(a0), "r"(a1), "r"(a2), "r"(a3), "r"(b0), "r"(b1));
}

// ---------------- layernorm ----------------
__global__ void __launch_bounds__(256) ln_kernel(const float* __restrict__ x,
                                                 const float* __restrict__ w,
                                                 const float* __restrict__ b) {
    int row = blockIdx.x;
    int tid = threadIdx.x;
    const float* xr = x + row*DIM;
    __shared__ float red[20];
    float v0 = xr[tid], v1 = xr[tid+256];
    float s = v0 + v1;
    #pragma unroll
    for (int o=16;o;o>>=1) s += __shfl_xor_sync(0xffffffffu, s, o);
    if ((tid&31)==0) red[tid>>5] = s;
    __syncthreads();
    if (tid < 8) {
        s = red[tid];
        #pragma unroll
        for (int o=4;o;o>>=1) s += __shfl_xor_sync(0xffu, s, o);
        if (tid==0) red[16] = s;
    }
    __syncthreads();
    float mu = red[16] * (1.0f/DIM);
    float d0 = v0-mu, d1 = v1-mu;
    float q = d0*d0 + d1*d1;
    #pragma unroll
    for (int o=16;o;o>>=1) q += __shfl_xor_sync(0xffffffffu, q, o);
    if ((tid&31)==0) red[8 + (tid>>5)] = q;
    __syncthreads();
    if (tid < 8) {
        q = red[8+tid];
        #pragma unroll
        for (int o=4;o;o>>=1) q += __shfl_xor_sync(0xffu, q, o);
        if (tid==0) red[17] = q;
    }
    __syncthreads();
    float inv = rsqrtf(red[17]*(1.0f/DIM) + 1e-5f);
    g_xn[row*DIM + tid]     = d0*inv*w[tid]     + b[tid];
    g_xn[row*DIM + tid+256] = d1*inv*w[tid+256] + b[tid+256];
}

// ---------------- generic tf32 MMA GEMM (double-buffered): C = A@B ----------------
// 128 threads = 4 warps (2m x 2n), warp tile m32 x n32, block tile 64x64, BK=32.
// Ping-pong smem + register prefetch: ONE barrier per chunk, LDG overlapped with MMA.
// EPI: 0 none, 2 C=AB+bias[col], 3 C=to_tf32(AB), 4 C=0.5*AB
struct SmemGemm { float sA[2][64][36]; float sB[2][32][72]; };

template<int EPI>
__device__ __forceinline__ void gemm_body(const float* __restrict__ A, const float* __restrict__ B,
                                          float* __restrict__ C, int N, int K,
                                          const float* __restrict__ add,
                                          SmemGemm& sm, int m0, int n0) {
    int tid = threadIdx.x;
    int warp = tid>>5, lane = tid&31;
    int qrow = lane>>2, qcol = lane&3;
    int m_base = (warp&1)*32, n_base = (warp>>1)*32;
    float acc[8][4] = {};
    float4 pa[4], pb[4];
    auto ldAB = [&](int kc) {
        #pragma unroll
        for (int q=0;q<4;q++) {
            int idx = q*128+tid; int r = idx>>3, c4 = idx&7;
            pa[q] = *(const float4*)(A + (size_t)(m0+r)*K + kc + c4*4);
        }
        #pragma unroll
        for (int q=0;q<4;q++) {
            int idx = q*128+tid; int r = idx>>4, c4 = idx&15;
            pb[q] = *(const float4*)(B + (size_t)(kc+r)*N + n0 + c4*4);
        }
    };
    auto stAB = [&](int buf) {
        #pragma unroll
        for (int q=0;q<4;q++) {
            int idx = q*128+tid; int r = idx>>3, c4 = idx&7;
            sm.sA[buf][r][c4*4+0]=to_tf32(pa[q].x); sm.sA[buf][r][c4*4+1]=to_tf32(pa[q].y);
            sm.sA[buf][r][c4*4+2]=to_tf32(pa[q].z); sm.sA[buf][r][c4*4+3]=to_tf32(pa[q].w);
        }
        #pragma unroll
        for (int q=0;q<4;q++) {
            int idx = q*128+tid; int r = idx>>4, c4 = idx&15;
            sm.sB[buf][r][c4*4+0]=to_tf32(pb[q].x); sm.sB[buf][r][c4*4+1]=to_tf32(pb[q].y);
            sm.sB[buf][r][c4*4+2]=to_tf32(pb[q].z); sm.sB[buf][r][c4*4+3]=to_tf32(pb[q].w);
        }
    };
    ldAB(0);
    stAB(0);
    if (K > 32) ldAB(32);
    __syncthreads();
    int cur = 0;
    for (int kc = 0; kc < K; kc += 32) {
        int nxt = cur^1;
        if (kc + 32 < K) {
            stAB(nxt);
            if (kc + 64 < K) ldAB(kc + 64);
        }
        #pragma unroll
        for (int ks=0; ks<4; ks++) {
            int k0 = ks*8;
            unsigned a[2][4];
            #pragma unroll
            for (int mf=0; mf<2; mf++) {
                int mr = m_base + mf*16 + qrow;
                a[mf][0] = __float_as_uint(sm.sA[cur][mr  ][k0+qcol  ]);
                a[mf][1] = __float_as_uint(sm.sA[cur][mr+8][k0+qcol  ]);
                a[mf][2] = __float_as_uint(sm.sA[cur][mr  ][k0+qcol+4]);
                a[mf][3] = __float_as_uint(sm.sA[cur][mr+8][k0+qcol+4]);
            }
            #pragma unroll
            for (int nf=0; nf<4; nf++) {
                unsigned b0 = __float_as_uint(sm.sB[cur][k0+qcol  ][n_base+nf*8+qrow]);
                unsigned b1 = __float_as_uint(sm.sB[cur][k0+qcol+4][n_base+nf*8+qrow]);
                mma_tf32(acc[nf],   a[0][0],a[0][1],a[0][2],a[0][3], b0,b1);
                mma_tf32(acc[4+nf], a[1][0],a[1][1],a[1][2],a[1][3], b0,b1);
            }
        }
        __syncthreads();
        cur = nxt;
    }
    #pragma unroll
    for (int mf=0; mf<2; mf++) {
        #pragma unroll
        for (int nf=0; nf<4; nf++) {
            int col = n0 + n_base + nf*8 + 2*qcol;
            int r0 = m0 + m_base + mf*16 + qrow, r1 = r0 + 8;
            float2 v0 = make_float2(acc[mf*4+nf][0], acc[mf*4+nf][1]);
            float2 v1 = make_float2(acc[mf*4+nf][2], acc[mf*4+nf][3]);
            if (EPI==2) {
                v0.x += add[col]; v0.y += add[col+1];
                v1.x += add[col]; v1.y += add[col+1];
            } else if (EPI==3) {
                v0.x = to_tf32(v0.x); v0.y = to_tf32(v0.y);
                v1.x = to_tf32(v1.x); v1.y = to_tf32(v1.y);
            } else if (EPI==4) {
                v0.x *= 0.5f; v0.y *= 0.5f;
                v1.x *= 0.5f; v1.y *= 0.5f;
            }
            *(float2*)(C + (size_t)r0*N + col) = v0;
            *(float2*)(C + (size_t)r1*N + col) = v1;
        }
    }
}

template<int EPI>
__global__ void __launch_bounds__(128) mma_gemm(const float* __restrict__ A, const float* __restrict__ B,
                                                float* __restrict__ C, int N, int K,
                                                const float* __restrict__ add) {
    __shared__ SmemGemm sm;
    gemm_body<EPI>(A, B, C, N, K, add, sm, blockIdx.y*64, blockIdx.x*64);
}

// fused qkv + q1/k1/v1 projections: 240 blocks, 1D grid.
__global__ void __launch_bounds__(128) fused_proj(const float* __restrict__ A,
                                                  const float* __restrict__ Wq,
                                                  const float* __restrict__ B0, const float* __restrict__ B1,
                                                  const float* __restrict__ B2,
                                                  float* Cq, float* C0, float* C1, float* C2) {
    __shared__ SmemGemm sm;
    int id = blockIdx.x;
    if (id < 192) {
        int x = id % 24, y = id / 24;
        gemm_body<0>(A, Wq, Cq, 1536, 512, nullptr, sm, y*64, x*64);
    } else {
        int t = id - 192;
        int z = t >> 4, r = t & 15;
        int x = r & 1, y = r >> 1;
        const float* B = z==0 ? B0 : (z==1 ? B1 : B2);
        float* C       = z==0 ? C0 : (z==1 ? C1 : C2);
        gemm_body<3>(A, B, C, 128, 512, nullptr, sm, y*64, x*64);
    }
}

// g_wcat rows 0..511 = 0.5*w_out
__global__ void __launch_bounds__(256) wcopy_kernel(const float* __restrict__ w) {
    int i = blockIdx.x*256 + threadIdx.x;
    float4 v = ((const float4*)w)[i];
    v.x *= 0.5f; v.y *= 0.5f; v.z *= 0.5f; v.w *= 0.5f;
    ((float4*)g_wcat)[i] = v;
}

// ---------------- per-diagonal rel-projection via tf32 MMA (frozen) ----------------
#define PBUF_FLOATS 2560
#define DIAG_SMEM (128*132*4 + 2*PBUF_FLOATS*4)

__global__ void __launch_bounds__(256,2) diag_mma(const float* __restrict__ Pq,
                                                  const float* __restrict__ Pk,
                                                  const float* __restrict__ Pv) {
    int d  = blockIdx.y;
    int nj = SEQ - d;
    int j0 = blockIdx.x * 128;
    if (j0 >= nj) return;
    int nvalid = min(128, nj - j0);

    extern __shared__ float dsm[];
    float (*sA)[132] = (float(*)[132])dsm;
    float* sB = dsm + 128*132;

    int tid = threadIdx.x, warp = tid>>5, lane = tid&31;
    int qrow = lane>>2, qcol = lane&3;
    int m_base = (warp&3)*32;
    bool act = m_base < nvalid;

    auto loadA = [&](const float* __restrict__ Ab, int rowbase) {
        __syncthreads();
        #pragma unroll
        for (int q=0;q<16;q++) {
            int idx = q*256+tid; int r = idx>>5, c4 = idx&31;
            float4 v = make_float4(0.f,0.f,0.f,0.f);
            if (r < nvalid) v = *(const float4*)(Ab + (rowbase+r)*HD + c4*4);
            *(float4*)&sA[r][c4*4] = v;
        }
    };

    auto gemm_h = [&](const float* __restrict__ P, int c0, float acc[8][4]) {
        int nf0 = (warp>>2)*4;
        int pr = tid>>4, L = tid&15;
        const float* Pt = P + pr*HD + c0 + L*4;
        int rowbase_f = ((pr>>3)*2 + ((pr>>2)&1))*32 + (pr&3);
        int nf_f = L>>1;
        int qoff = (L&1)*4;
        auto stchunk = [&](float* buf, float4 v) {
            buf[(rowbase_f + (qoff+0)*4)*12 + nf_f] = to_tf32(v.x);
            buf[(rowbase_f + (qoff+1)*4)*12 + nf_f] = to_tf32(v.y);
            buf[(rowbase_f + (qoff+2)*4)*12 + nf_f] = to_tf32(v.z);
            buf[(rowbase_f + (qoff+3)*4)*12 + nf_f] = to_tf32(v.w);
        };
        float4 pre = *(const float4*)Pt;
        stchunk(sB, pre);
        pre = *(const float4*)(Pt + 16*HD);
        __syncthreads();
        int cur = 0;
        for (int kc=0; kc<128; kc+=16) {
            int nxt = cur^1;
            if (kc + 16 < 128) {
                stchunk(sB + nxt*PBUF_FLOATS, pre);
                if (kc + 32 < 128) pre = *(const float4*)(Pt + (kc+32)*HD);
            }
            if (act) {
                const float* buf = sB + cur*PBUF_FLOATS;
                #pragma unroll
                for (int ks=0; ks<2; ks++) {
                    int k0 = kc + ks*8;
                    unsigned a[2][4];
                    #pragma unroll
                    for (int mf=0; mf<2; mf++) {
                        int mr = m_base + mf*16 + qrow;
                        a[mf][0] = __float_as_uint(sA[mr  ][k0+qcol  ]);
                        a[mf][1] = __float_as_uint(sA[mr+8][k0+qcol  ]);
                        a[mf][2] = __float_as_uint(sA[mr  ][k0+qcol+4]);
                        a[mf][3] = __float_as_uint(sA[mr+8][k0+qcol+4]);
                    }
                    float4 b0p = *(const float4*)(buf + ((ks*2+0)*32 + lane)*12 + nf0);
                    float4 b1p = *(const float4*)(buf + ((ks*2+1)*32 + lane)*12 + nf0);
                    const float* b0a = (const float*)&b0p;
                    const float* b1a = (const float*)&b1p;
                    #pragma unroll
                    for (int nf=0; nf<4; nf++) {
                        unsigned b0 = __float_as_uint(b0a[nf]);
                        unsigned b1 = __float_as_uint(b1a[nf]);
                        mma_tf32(acc[nf],   a[0][0],a[0][1],a[0][2],a[0][3], b0,b1);
                        mma_tf32(acc[4+nf], a[1][0],a[1][1],a[1][2],a[1][3], b0,b1);
                    }
                }
            }
            __syncthreads();
            cur = nxt;
        }
    };

    auto dots2_h = [&](float accQ[8][4], float accK[8][4], int half) {
        if (!act) return;
        #pragma unroll
        for (int mf=0; mf<2; mf++) {
            #pragma unroll
            for (int hh=0; hh<2; hh++) {
                int f0 = mf*4 + 2*hh, f1 = f0 + 1;
                float p0 = accQ[f0][0]*accK[f0][0] + accQ[f0][1]*accK[f0][1]
                         + accQ[f1][0]*accK[f1][0] + accQ[f1][1]*accK[f1][1];
                float p1 = accQ[f0][2]*accK[f0][2] + accQ[f0][3]*accK[f0][3]
                         + accQ[f1][2]*accK[f1][2] + accQ[f1][3]*accK[f1][3];
                p0 += __shfl_xor_sync(0xffffffffu, p0, 1);
                p0 += __shfl_xor_sync(0xffffffffu, p0, 2);
                p1 += __shfl_xor_sync(0xffffffffu, p1, 1);
                p1 += __shfl_xor_sync(0xffffffffu, p1, 2);
                if (qcol == 0) {
                    int h = half*4 + ((warp>>2)<<1) + hh;
                    int r0 = m_base + mf*16 + qrow;
                    if (r0 < nvalid) { int j = j0 + r0; g_dots[(size_t)h*SEQ*SEQ + (size_t)(j+d)*SEQ + j] = p0; }
                    int r1 = r0 + 8;
                    if (r1 < nvalid) { int j = j0 + r1; g_dots[(size_t)h*SEQ*SEQ + (size_t)(j+d)*SEQ + j] = p1; }
                }
            }
        }
    };

    const float* Pk_d = Pk + (size_t)d*HD*HD;
    const float* Pq_d = Pq + (size_t)(SEQ-1-d)*HD*HD;

    float accK[8][4], accQ[8][4];

    #pragma unroll
    for (int f=0;f<8;f++){accK[f][0]=0;accK[f][1]=0;accK[f][2]=0;accK[f][3]=0;}
    loadA(g_ak, j0);
    gemm_h(Pk_d, 0, accK);
    #pragma unroll
    for (int f=0;f<8;f++){accQ[f][0]=0;accQ[f][1]=0;accQ[f][2]=0;accQ[f][3]=0;}
    loadA(g_aq, j0 + d);
    gemm_h(Pq_d, 0, accQ);
    dots2_h(accQ, accK, 0);

    #pragma unroll
    for (int f=0;f<8;f++){accQ[f][0]=0;accQ[f][1]=0;accQ[f][2]=0;accQ[f][3]=0;}
    gemm_h(Pq_d, 64, accQ);
    #pragma unroll
    for (int f=0;f<8;f++){accK[f][0]=0;accK[f][1]=0;accK[f][2]=0;accK[f][3]=0;}
    loadA(g_ak, j0);
    gemm_h(Pk_d, 64, accK);
    dots2_h(accQ, accK, 1);

    {
        int nf0 = (warp>>2)*8;
        float acc[16][4];
        #pragma unroll
        for (int f=0;f<16;f++){acc[f][0]=0;acc[f][1]=0;acc[f][2]=0;acc[f][3]=0;}
        loadA(g_av, j0);
        const float* P = Pv + (size_t)d*HD*HD;
        int pr = tid>>5, pc4 = tid&31;
        const float* Pt = P + pr*HD + pc4*4;
        int khalf_f = (pr>>2)&1, kq_f = pr&3;
        int nf_f = pc4>>1;
        int qoff = (pc4&1)*4;
        auto stchunkV = [&](float* buf, float4 v, int q) {
            int rowbase_f = (q*2 + khalf_f)*32 + kq_f;
            buf[(rowbase_f + (qoff+0)*4)*20 + nf_f] = to_tf32(v.x);
            buf[(rowbase_f + (qoff+1)*4)*20 + nf_f] = to_tf32(v.y);
            buf[(rowbase_f + (qoff+2)*4)*20 + nf_f] = to_tf32(v.z);
            buf[(rowbase_f + (qoff+3)*4)*20 + nf_f] = to_tf32(v.w);
        };
        float4 pre[2];
        #pragma unroll
        for (int q=0;q<2;q++) pre[q] = *(const float4*)(Pt + q*8*HD);
        #pragma unroll
        for (int q=0;q<2;q++) stchunkV(sB, pre[q], q);
        #pragma unroll
        for (int q=0;q<2;q++) pre[q] = *(const float4*)(Pt + (16 + q*8)*HD);
        __syncthreads();
        int cur = 0;
        for (int kc=0; kc<128; kc+=16) {
            int nxt = cur^1;
            if (kc + 16 < 128) {
                #pragma unroll
                for (int q=0;q<2;q++) stchunkV(sB + nxt*PBUF_FLOATS, pre[q], q);
                if (kc + 32 < 128) {
                    #pragma unroll
                    for (int q=0;q<2;q++) pre[q] = *(const float4*)(Pt + (kc+32+q*8)*HD);
                }
            }
            if (act) {
                const float* buf = sB + cur*PBUF_FLOATS;
                #pragma unroll
                for (int ks=0; ks<2; ks++) {
                    int k0 = kc + ks*8;
                    unsigned a[2][4];
                    #pragma unroll
                    for (int mf=0; mf<2; mf++) {
                        int mr = m_base + mf*16 + qrow;
                        a[mf][0] = __float_as_uint(sA[mr  ][k0+qcol  ]);
                        a[mf][1] = __float_as_uint(sA[mr+8][k0+qcol  ]);
                        a[mf][2] = __float_as_uint(sA[mr  ][k0+qcol+4]);
                        a[mf][3] = __float_as_uint(sA[mr+8][k0+qcol+4]);
                    }
                    float4 b0p0 = *(const float4*)(buf + ((ks*2+0)*32 + lane)*20 + nf0);
                    float4 b0p1 = *(const float4*)(buf + ((ks*2+0)*32 + lane)*20 + nf0 + 4);
                    float4 b1p0 = *(const float4*)(buf + ((ks*2+1)*32 + lane)*20 + nf0);
                    float4 b1p1 = *(const float4*)(buf + ((ks*2+1)*32 + lane)*20 + nf0 + 4);
                    const float* b0a = (const float*)&b0p0;
                    const float* b0b = (const float*)&b0p1;
                    const float* b1a = (const float*)&b1p0;
                    const float* b1b = (const float*)&b1p1;
                    #pragma unroll
                    for (int nf=0; nf<8; nf++) {
                        unsigned b0 = __float_as_uint(nf < 4 ? b0a[nf] : b0b[nf-4]);
                        unsigned b1 = __float_as_uint(nf < 4 ? b1a[nf] : b1b[nf-4]);
                        mma_tf32(acc[nf],   a[0][0],a[0][1],a[0][2],a[0][3], b0,b1);
                        mma_tf32(acc[8+nf], a[1][0],a[1][1],a[1][2],a[1][3], b0,b1);
                    }
                }
            }
            __syncthreads();
            cur = nxt;
        }
        if (act) {
            int n_base = (warp>>2)*64;
            #pragma unroll
            for (int mf=0; mf<2; mf++) {
                #pragma unroll
                for (int nf=0; nf<8; nf++) {
                    int col = n_base + nf*8 + 2*qcol;
                    int r0 = m_base + mf*16 + qrow;
                    if (r0 < nvalid)
                        *(float2*)(g_uv + ((size_t)d*SEQ + j0 + r0)*HD + col) = make_float2(acc[mf*8+nf][0], acc[mf*8+nf][1]);
                    int r1 = r0 + 8;
                    if (r1 < nvalid)
                        *(float2*)(g_uv + ((size_t)d*SEQ + j0 + r1)*HD + col) = make_float2(acc[mf*8+nf][2], acc[mf*8+nf][3]);
                }
            }
        }
    }
}

// ---------------- dots1 + combine + causal softmax + fused out1 -> g_cat ----------------
__global__ void __launch_bounds__(256) attn_kernel() {
    int h  = blockIdx.y;
    int i0 = blockIdx.x * 16;
    __shared__ float sQ[16][68];
    __shared__ float sK[32][68];
    __shared__ float sD[16][512];
    int tid = threadIdx.x;
    {   int r = tid>>4, c4 = tid&15;
        *(float4*)&sQ[r][c4*4] = *(const float4*)(g_qkv + (i0+r)*1536 + h*64 + c4*4); }
    int r2 = tid>>4, jj = tid&15;
    for (int jc = 0; jc < 512; jc += 32) {
        __syncthreads();
        #pragma unroll
        for (int q=0; q<2; q++) {
            int idx = q*256 + tid; int r = idx>>4, c4 = idx&15;
            *(float4*)&sK[r][c4*4] = *(const float4*)(g_qkv + (jc+r)*1536 + 512 + h*64 + c4*4);
        }
        __syncthreads();
        float a0 = 0.f, a1 = 0.f;
        #pragma unroll
        for (int c4 = 0; c4 < 16; c4++) {
            float4 qv = *(const float4*)&sQ[r2][c4*4];
            float4 k0 = *(const float4*)&sK[jj][c4*4];
            float4 k1 = *(const float4*)&sK[jj+16][c4*4];
            a0 += qv.x*k0.x + qv.y*k0.y + qv.z*k0.z + qv.w*k0.w;
            a1 += qv.x*k1.x + qv.y*k1.y + qv.z*k1.z + qv.w*k1.w;
        }
        sD[r2][jc+jj]    = a0;
        sD[r2][jc+jj+16] = a1;
    }
    __syncthreads();
    int w = tid>>5, lane = tid&31;
    for (int rr = 2*w; rr < 2*w+2; rr++) {
        int i = i0 + rr;
        float vals[16];
        float m = -1e30f;
        #pragma unroll
        for (int t=0; t<16; t++) {
            int j = lane + t*32;
            float dv = -1e30f;
            if (j <= i)
                dv = 0.0625f * (sD[rr][j] + g_dots[(size_t)h*SEQ*SEQ + (size_t)i*SEQ + j]);
            vals[t] = dv;
            m = fmaxf(m, dv);
        }
        #pragma unroll
        for (int o=16;o;o>>=1) m = fmaxf(m, __shfl_xor_sync(0xffffffffu, m, o));
        float s = 0.f;
        #pragma unroll
        for (int t=0; t<16; t++) {
            float e = (vals[t] > -1e29f) ? __expf(vals[t]-m) : 0.f;
            vals[t] = e; s += e;
        }
        #pragma unroll
        for (int o=16;o;o>>=1) s += __shfl_xor_sync(0xffffffffu, s, o);
        float inv = 1.f / s;
        #pragma unroll
        for (int t=0; t<16; t++) {
            int j = lane + t*32;
            float av = vals[t]*inv;
            g_dots[(size_t)h*SEQ*SEQ + (size_t)i*SEQ + j] = av;
            sD[rr][j] = av;
        }
    }
    __syncthreads();
    // fused out1 -> g_cat cols [h*64, h*64+64), row stride 640
    {
        int tx = tid & 15;
        float acc0=0.f, acc1=0.f, acc2=0.f, acc3=0.f;
        for (int jc = 0; jc < 512; jc += 32) {
            __syncthreads();
            #pragma unroll
            for (int q=0; q<2; q++) {
                int idx = q*256 + tid; int r = idx>>4, c4 = idx&15;
                *(float4*)&sK[r][c4*4] = *(const float4*)(g_qkv + (jc+r)*1536 + 1024 + h*64 + c4*4);
            }
            __syncthreads();
            #pragma unroll
            for (int k=0; k<32; k++) {
                float a = sD[r2][jc+k];
                float4 v4 = *(float4*)&sK[k][tx*4];
                acc0 += a*v4.x; acc1 += a*v4.y; acc2 += a*v4.z; acc3 += a*v4.w;
            }
        }
        *(float4*)(g_cat + (size_t)(i0+r2)*640 + h*64 + tx*4) = make_float4(acc0,acc1,acc2,acc3);
    }
}

// ---------------- out2 -> g_cat cols [512, 640) ----------------
__global__ void __launch_bounds__(1024) out2_kernel() {
    int i = blockIdx.x;
    int tid = threadIdx.x;
    int c = tid & 127;
    int part = tid >> 7;
    int h = c >> 4;
    const float* arow = g_dots + (size_t)h*SEQ*SEQ + (size_t)i*SEQ;
    int len = i + 1;
    int chunk = (len + 7) >> 3;
    int jb = part*chunk, je = min(len, jb + chunk);
    float a0=0.f, a1=0.f, a2=0.f, a3=0.f;
    int j = jb;
    for (; j+4 <= je; j += 4) {
        a0 += arow[j]   * g_uv[((size_t)(i-j  )*SEQ + j  )*HD + c];
        a1 += arow[j+1] * g_uv[((size_t)(i-j-1)*SEQ + j+1)*HD + c];
        a2 += arow[j+2] * g_uv[((size_t)(i-j-2)*SEQ + j+2)*HD + c];
        a3 += arow[j+3] * g_uv[((size_t)(i-j-3)*SEQ + j+3)*HD + c];
    }
    for (; j < je; j++)
        a0 += arow[j] * g_uv[((size_t)(i-j)*SEQ + j)*HD + c];
    __shared__ float red[1024];
    red[tid] = (a0+a1) + (a2+a3);
    __syncthreads();
    if (part < 4) red[tid] += red[tid + 512];
    __syncthreads();
    if (part < 2) red[tid] += red[tid + 256];
    __syncthreads();
    if (part == 0)
        g_cat[(size_t)i*640 + 512 + c] = red[c] + red[c + 128];
}

// ---------------- launch ----------------
extern "C" void kernel_launch(void* const* d_in, const int* in_sizes, int n_in,
                              void* d_out, int out_size) {
    const float* x     = (const float*)d_in[0];
    const float* ln_w  = (const float*)d_in[1];
    const float* ln_b  = (const float*)d_in[2];
    const float* w_qkv = (const float*)d_in[3];
    const float* w_q1  = (const float*)d_in[4];
    const float* p_q2  = (const float*)d_in[5];
    const float* w_k1  = (const float*)d_in[6];
    const float* p_k2  = (const float*)d_in[7];
    const float* w_v1  = (const float*)d_in[8];
    const float* p_v2  = (const float*)d_in[9];
    const float* w_v3  = (const float*)d_in[10];
    const float* w_out = (const float*)d_in[11];
    const float* b_out = (const float*)d_in[12];
    float* out = (float*)d_out;

    float *p_xn, *p_qkvb, *p_aq, *p_ak, *p_av, *p_cat, *p_wcat;
    cudaGetSymbolAddress((void**)&p_xn,   g_xn);
    cudaGetSymbolAddress((void**)&p_qkvb, g_qkv);
    cudaGetSymbolAddress((void**)&p_aq,   g_aq);
    cudaGetSymbolAddress((void**)&p_ak,   g_ak);
    cudaGetSymbolAddress((void**)&p_av,   g_av);
    cudaGetSymbolAddress((void**)&p_cat,  g_cat);
    cudaGetSymbolAddress((void**)&p_wcat, g_wcat);

    cudaFuncSetAttribute(diag_mma, cudaFuncAttributeMaxDynamicSharedMemorySize, DIAG_SMEM);

    // weight prep (inputs only; off the critical path)
    wcopy_kernel<<<256, 256>>>(w_out);
    mma_gemm<4><<<dim3(8,2), 128>>>(w_v3, w_out, p_wcat + 512*512, 512, 512, nullptr);

    ln_kernel<<<512, 256>>>(x, ln_w, ln_b);

    fused_proj<<<240, 128>>>(p_xn, w_qkv, w_q1, w_k1, w_v1,
                             p_qkvb, p_aq, p_ak, p_av);

    diag_mma<<<dim3(4,512), 256, DIAG_SMEM>>>(p_q2, p_k2, p_v2);

    attn_kernel<<<dim3(32,8), 256>>>();
    out2_kernel<<<512, 1024>>>();

    mma_gemm<2><<<dim3(8,8), 128>>>(p_cat, p_wcat, out, 512, 640, b_out);
}